// round 8
// baseline (speedup 1.0000x reference)
#include <cuda_runtime.h>

typedef unsigned long long u64;

__device__ __forceinline__ u64 pk2(float lo, float hi){
  u64 r; asm volatile("mov.b64 %0, {%1,%2};" : "=l"(r) : "f"(lo), "f"(hi)); return r;
}
__device__ __forceinline__ void upk2(u64 v, float& lo, float& hi){
  asm("mov.b64 {%0,%1}, %2;" : "=f"(lo), "=f"(hi) : "l"(v));
}
__device__ __forceinline__ u64 fma2(u64 a, u64 b, u64 c){
  u64 d; asm("fma.rn.f32x2 %0, %1, %2, %3;" : "=l"(d) : "l"(a), "l"(b), "l"(c)); return d;
}
__device__ __forceinline__ u64 mul2(u64 a, u64 b){
  u64 d; asm("mul.rn.f32x2 %0, %1, %2;" : "=l"(d) : "l"(a), "l"(b)); return d;
}
__device__ __forceinline__ u64 add2(u64 a, u64 b){
  u64 d; asm("add.rn.f32x2 %0, %1, %2;" : "=l"(d) : "l"(a), "l"(b)); return d;
}

__device__ __forceinline__ unsigned smem_u32(const void* p){
  unsigned a;
  asm("{ .reg .u64 t; cvta.to.shared.u64 t, %1; cvt.u32.u64 %0, t; }" : "=r"(a) : "l"(p));
  return a;
}

// 16 rows per CTA stored as 4 quads of 4 rows; one 16B slot per (position, quad).
// slot = (quad ^ (p>>1) ^ (p>>3)) & 3. (R5 layout — address math stays uniform.)
__device__ __forceinline__ int widx(int pos, int quad){
  return (pos << 4) + (((quad ^ (pos >> 1) ^ (pos >> 3)) & 3) << 2);
}

// Butterfly on one pair of positions for 4 rows (2 packed f32x2 lanes each).
__device__ __forceinline__ void bflyq(u64& x0a, u64& x0b, u64& x1a, u64& x1b,
                                      const float* t){
  u64 m0 = pk2(t[0], t[0]);
  u64 m1 = pk2(t[1], t[1]);
  u64 m2 = pk2(t[2], t[2]);
  u64 m3 = pk2(t[3], t[3]);
  u64 a = x0a, b = x1a;
  x0a = fma2(m0, a, mul2(m1, b));
  x1a = fma2(m2, a, mul2(m3, b));
  a = x0b; b = x1b;
  x0b = fma2(m0, a, mul2(m1, b));
  x1b = fma2(m2, a, mul2(m3, b));
}

// 3 stages on 8 local elements (local strides 1,2,4).
__device__ __forceinline__ void radix8q(u64 v01[8], u64 v23[8], const float tw[48]){
  bflyq(v01[0],v23[0], v01[1],v23[1], tw+ 0);
  bflyq(v01[2],v23[2], v01[3],v23[3], tw+ 4);
  bflyq(v01[4],v23[4], v01[5],v23[5], tw+ 8);
  bflyq(v01[6],v23[6], v01[7],v23[7], tw+12);
  bflyq(v01[0],v23[0], v01[2],v23[2], tw+16);
  bflyq(v01[1],v23[1], v01[3],v23[3], tw+20);
  bflyq(v01[4],v23[4], v01[6],v23[6], tw+24);
  bflyq(v01[5],v23[5], v01[7],v23[7], tw+28);
  bflyq(v01[0],v23[0], v01[4],v23[4], tw+32);
  bflyq(v01[1],v23[1], v01[5],v23[5], tw+36);
  bflyq(v01[2],v23[2], v01[6],v23[6], tw+40);
  bflyq(v01[3],v23[3], v01[7],v23[7], tw+44);
}

__device__ __forceinline__ void load_tw(const float4* __restrict__ tw4,
                                        int s0, int pbase, int pstride, float tw[48]){
  #pragma unroll
  for (int s = 0; s < 3; s++){
    #pragma unroll
    for (int i = 0; i < 4; i++){
      float4 t = tw4[(s0 + s) * 512 + pbase + i * pstride];
      tw[(s*4+i)*4+0] = t.x; tw[(s*4+i)*4+1] = t.y;
      tw[(s*4+i)*4+2] = t.z; tw[(s*4+i)*4+3] = t.w;
    }
  }
}

// Data tile: 16384 floats (64KB). Twiddle stash (stages 6-9): 8192 floats (32KB).
#define TW_OFF 16384

__global__ __launch_bounds__(256, 2)
void butterfly_kernel(const float* __restrict__ x,
                      const float* __restrict__ twg,
                      const float* __restrict__ bias,
                      float* __restrict__ out)
{
  extern __shared__ float sdata[];   // 96KB: data tile + stage6-9 twiddle stash
  const float4* tw4 = (const float4*)twg;
  const int tid = threadIdx.x;
  const int o   = tid & 127;         // position-octet index (P1/P2)
  const int sub = tid >> 7;          // which 8 of the 16 rows (P1/P2)
  const long long rowbase = (long long)blockIdx.x * 16 + sub * 8;

  // ---- async prefetch of stage 6-9 twiddles (32KB) into smem; overlaps P1+P2
  {
    const float4* src = tw4 + 6 * 512;           // 2048 float4
    unsigned dst = smem_u32(&sdata[TW_OFF]);
    #pragma unroll
    for (int i = 0; i < 8; i++){
      int idx = tid + 256 * i;
      asm volatile("cp.async.cg.shared.global [%0], [%1], 16;"
                   :: "r"(dst + idx * 16), "l"(src + idx));
    }
    asm volatile("cp.async.commit_group;");
  }

  float tw[48];

  // ================= PASS 1: stages 0-2 (stride 1,2,4), global -> smem ======
  load_tw(tw4, 0, 4 * o, 1, tw);
  #pragma unroll
  for (int g = 0; g < 2; g++){
    const int quad = 2 * sub + g;    // quad q holds rows blk*16 + 4q + {0..3}
    const float* base = x + (rowbase + 4 * g) * 1024 + 8 * o;
    float4 a0 = __ldcs((const float4*)(base        ));
    float4 b0 = __ldcs((const float4*)(base +    4 ));
    float4 a1 = __ldcs((const float4*)(base + 1024 ));
    float4 b1 = __ldcs((const float4*)(base + 1028 ));
    float4 a2 = __ldcs((const float4*)(base + 2048 ));
    float4 b2 = __ldcs((const float4*)(base + 2052 ));
    float4 a3 = __ldcs((const float4*)(base + 3072 ));
    float4 b3 = __ldcs((const float4*)(base + 3076 ));
    u64 v01[8], v23[8];
    v01[0]=pk2(a0.x,a1.x); v01[1]=pk2(a0.y,a1.y); v01[2]=pk2(a0.z,a1.z); v01[3]=pk2(a0.w,a1.w);
    v01[4]=pk2(b0.x,b1.x); v01[5]=pk2(b0.y,b1.y); v01[6]=pk2(b0.z,b1.z); v01[7]=pk2(b0.w,b1.w);
    v23[0]=pk2(a2.x,a3.x); v23[1]=pk2(a2.y,a3.y); v23[2]=pk2(a2.z,a3.z); v23[3]=pk2(a2.w,a3.w);
    v23[4]=pk2(b2.x,b3.x); v23[5]=pk2(b2.y,b3.y); v23[6]=pk2(b2.z,b3.z); v23[7]=pk2(b2.w,b3.w);

    radix8q(v01, v23, tw);

    #pragma unroll
    for (int c = 0; c < 8; c++){
      ulonglong2 u; u.x = v01[c]; u.y = v23[c];
      *(ulonglong2*)&sdata[widx(8 * o + c, quad)] = u;
    }
  }

  // Hoist P2 twiddle loads above the barrier (independent of smem).
  const int bb = o >> 3, j = o & 7;
  load_tw(tw4, 3, 32 * bb + j, 8, tw);
  __syncthreads();

  // ================= PASS 2: stages 3-5 (stride 8,16,32) ====================
  {
    #pragma unroll
    for (int g = 0; g < 2; g++){
      const int quad = 2 * sub + g;
      u64 v01[8], v23[8];
      #pragma unroll
      for (int k = 0; k < 8; k++){
        ulonglong2 u = *(ulonglong2*)&sdata[widx(64 * bb + 8 * k + j, quad)];
        v01[k] = u.x; v23[k] = u.y;
      }
      radix8q(v01, v23, tw);
      #pragma unroll
      for (int k = 0; k < 8; k++){
        ulonglong2 u; u.x = v01[k]; u.y = v23[k];
        *(ulonglong2*)&sdata[widx(64 * bb + 8 * k + j, quad)] = u;
      }
    }
  }

  // Hoist bias loads above the barrier (independent of smem).
  const int j2 = tid & 63;
  const int q  = tid >> 6;
  float bs[16];
  #pragma unroll
  for (int m = 0; m < 16; m++) bs[m] = bias[j2 + 64 * m];

  // Prefetched twiddles are long since arrived; drain the group, then publish
  // via the barrier.
  asm volatile("cp.async.wait_group 0;");
  __syncthreads();

  // ====== PASS 3: stages 6-9 (stride 64,128,256,512) + bias -> global =======
  // Thread owns pos = j2 + 64m, m=0..15, for one quad (4 rows). All four
  // stages run in registers; twiddles come from the smem stash (LDS, 29cyc,
  // lane-contiguous -> conflict-free).
  {
    const float4* stw = (const float4*)&sdata[TW_OFF];
    u64 v01[16], v23[16];
    #pragma unroll
    for (int m = 0; m < 16; m++){
      ulonglong2 u = *(ulonglong2*)&sdata[widx(j2 + 64 * m, q)];
      v01[m] = u.x; v23[m] = u.y;
    }
    // stage 6 (S=64): pairs (2r, 2r+1); tw idx = 64r + j2
    #pragma unroll
    for (int r = 0; r < 8; r++){
      float4 t = stw[0 * 512 + 64 * r + j2];
      float tm[4] = {t.x, t.y, t.z, t.w};
      bflyq(v01[2*r], v23[2*r], v01[2*r+1], v23[2*r+1], tm);
    }
    // stage 7 (S=128): pairs (4r+h, 4r+h+2); tw idx = 128r + 64h + j2
    #pragma unroll
    for (int r = 0; r < 4; r++){
      #pragma unroll
      for (int h = 0; h < 2; h++){
        float4 t = stw[1 * 512 + 128 * r + 64 * h + j2];
        float tm[4] = {t.x, t.y, t.z, t.w};
        const int m0 = 4 * r + h;
        bflyq(v01[m0], v23[m0], v01[m0+2], v23[m0+2], tm);
      }
    }
    // stage 8 (S=256): pairs (8r+h, 8r+h+4); tw idx = 256r + 64h + j2
    #pragma unroll
    for (int r = 0; r < 2; r++){
      #pragma unroll
      for (int h = 0; h < 4; h++){
        float4 t = stw[2 * 512 + 256 * r + 64 * h + j2];
        float tm[4] = {t.x, t.y, t.z, t.w};
        const int m0 = 8 * r + h;
        bflyq(v01[m0], v23[m0], v01[m0+4], v23[m0+4], tm);
      }
    }
    // stage 9 (S=512): pairs (h, h+8); tw idx = 64h + j2
    #pragma unroll
    for (int h = 0; h < 8; h++){
      float4 t = stw[3 * 512 + 64 * h + j2];
      float tm[4] = {t.x, t.y, t.z, t.w};
      bflyq(v01[h], v23[h], v01[h+8], v23[h+8], tm);
    }
    // bias + store (lanes j2 consecutive -> 128B-coalesced STG.32, streaming)
    const long long r0 = (long long)blockIdx.x * 16 + 4 * q;
    float* obase = out + r0 * 1024 + j2;
    #pragma unroll
    for (int m = 0; m < 16; m++){
      u64 b2 = pk2(bs[m], bs[m]);
      u64 ylo = add2(v01[m], b2);
      u64 yhi = add2(v23[m], b2);
      float f0, f1, f2, f3;
      upk2(ylo, f0, f1); upk2(yhi, f2, f3);
      float* op = obase + 64 * m;
      __stcs(op,        f0);
      __stcs(op + 1024, f1);
      __stcs(op + 2048, f2);
      __stcs(op + 3072, f3);
    }
  }
}

extern "C" void kernel_launch(void* const* d_in, const int* in_sizes, int n_in,
                              void* d_out, int out_size)
{
  const float* x    = (const float*)d_in[0];   // (32768, 1024) f32
  const float* tw   = (const float*)d_in[1];   // (1, 10, 512, 2, 2) f32
  const float* bias = (const float*)d_in[2];   // (1024,) f32
  float* out = (float*)d_out;                  // (32768, 1024) f32

  const int batch = in_sizes[0] / 1024;
  const int smem_bytes = (16384 + 8192) * 4;   // 64KB data + 32KB twiddle stash

  cudaFuncSetAttribute(butterfly_kernel,
                       cudaFuncAttributeMaxDynamicSharedMemorySize, smem_bytes);
  butterfly_kernel<<<batch / 16, 256, smem_bytes>>>(x, tw, bias, out);
}

// round 9
// speedup vs baseline: 1.1204x; 1.1204x over previous
#include <cuda_runtime.h>

typedef unsigned long long u64;

__device__ __forceinline__ u64 pk2(float lo, float hi){
  u64 r; asm volatile("mov.b64 %0, {%1,%2};" : "=l"(r) : "f"(lo), "f"(hi)); return r;
}
__device__ __forceinline__ void upk2(u64 v, float& lo, float& hi){
  asm("mov.b64 {%0,%1}, %2;" : "=f"(lo), "=f"(hi) : "l"(v));
}
__device__ __forceinline__ u64 fma2(u64 a, u64 b, u64 c){
  u64 d; asm("fma.rn.f32x2 %0, %1, %2, %3;" : "=l"(d) : "l"(a), "l"(b), "l"(c)); return d;
}
__device__ __forceinline__ u64 mul2(u64 a, u64 b){
  u64 d; asm("mul.rn.f32x2 %0, %1, %2;" : "=l"(d) : "l"(a), "l"(b)); return d;
}
__device__ __forceinline__ u64 add2(u64 a, u64 b){
  u64 d; asm("add.rn.f32x2 %0, %1, %2;" : "=l"(d) : "l"(a), "l"(b)); return d;
}

// 16 rows per CTA stored as 4 quads of 4 rows; one 16B slot per (position, quad).
// slot = (quad ^ (p>>1) ^ (p>>3)) & 3. (R5 layout — address math stays uniform.)
__device__ __forceinline__ int widx(int pos, int quad){
  return (pos << 4) + (((quad ^ (pos >> 1) ^ (pos >> 3)) & 3) << 2);
}

// Butterfly on one pair of positions for 4 rows (2 packed f32x2 lanes each).
__device__ __forceinline__ void bflyq(u64& x0a, u64& x0b, u64& x1a, u64& x1b,
                                      const float* t){
  u64 m0 = pk2(t[0], t[0]);
  u64 m1 = pk2(t[1], t[1]);
  u64 m2 = pk2(t[2], t[2]);
  u64 m3 = pk2(t[3], t[3]);
  u64 a = x0a, b = x1a;
  x0a = fma2(m0, a, mul2(m1, b));
  x1a = fma2(m2, a, mul2(m3, b));
  a = x0b; b = x1b;
  x0b = fma2(m0, a, mul2(m1, b));
  x1b = fma2(m2, a, mul2(m3, b));
}

// 3 stages on 8 local elements (local strides 1,2,4).
__device__ __forceinline__ void radix8q(u64 v01[8], u64 v23[8], const float tw[48]){
  bflyq(v01[0],v23[0], v01[1],v23[1], tw+ 0);
  bflyq(v01[2],v23[2], v01[3],v23[3], tw+ 4);
  bflyq(v01[4],v23[4], v01[5],v23[5], tw+ 8);
  bflyq(v01[6],v23[6], v01[7],v23[7], tw+12);
  bflyq(v01[0],v23[0], v01[2],v23[2], tw+16);
  bflyq(v01[1],v23[1], v01[3],v23[3], tw+20);
  bflyq(v01[4],v23[4], v01[6],v23[6], tw+24);
  bflyq(v01[5],v23[5], v01[7],v23[7], tw+28);
  bflyq(v01[0],v23[0], v01[4],v23[4], tw+32);
  bflyq(v01[1],v23[1], v01[5],v23[5], tw+36);
  bflyq(v01[2],v23[2], v01[6],v23[6], tw+40);
  bflyq(v01[3],v23[3], v01[7],v23[7], tw+44);
}

__device__ __forceinline__ void load_tw(const float4* __restrict__ tw4,
                                        int s0, int pbase, int pstride, float tw[48]){
  #pragma unroll
  for (int s = 0; s < 3; s++){
    #pragma unroll
    for (int i = 0; i < 4; i++){
      float4 t = tw4[(s0 + s) * 512 + pbase + i * pstride];
      tw[(s*4+i)*4+0] = t.x; tw[(s*4+i)*4+1] = t.y;
      tw[(s*4+i)*4+2] = t.z; tw[(s*4+i)*4+3] = t.w;
    }
  }
}

// Data tile: 16384 floats (64KB).
// Padded stage0-2 twiddle stash: float4 p of stage s lives at float offset
// TWF + s*2560 + 4p + 4*(p>>2)  (80B lane stride for the 64B consumer stride
// -> bank-quads (5*lane + q) mod 8 all distinct -> conflict-free LDS.128).
#define TWF 16384
#define TWS 2560

__global__ __launch_bounds__(256, 2)
void butterfly_kernel(const float* __restrict__ x,
                      const float* __restrict__ twg,
                      const float* __restrict__ bias,
                      float* __restrict__ out)
{
  extern __shared__ float sdata[];   // 64KB data tile + 30KB padded tw stash
  const float4* tw4 = (const float4*)twg;
  const int tid = threadIdx.x;
  const int o   = tid & 127;         // position-octet index (P1/P2)
  const int sub = tid >> 7;          // which 8 of the 16 rows (P1/P2)
  const long long rowbase = (long long)blockIdx.x * 16 + sub * 8;

  // ---- Stage the stage-0..2 twiddles coalesced into padded smem (once) ----
  // 1536 float4, 6 per thread. Replaces P1's 64B-lane-stride LDGs (16 wf/inst).
  #pragma unroll
  for (int i = 0; i < 6; i++){
    int p  = tid + 256 * i;
    float4 t = tw4[p];
    int s  = p >> 9;
    int pp = p & 511;
    *(float4*)&sdata[TWF + s * TWS + 4 * pp + 4 * (pp >> 2)] = t;
  }
  __syncthreads();

  float tw[48];

  // ================= PASS 1: stages 0-2 (stride 1,2,4), global -> smem ======
  // Twiddles from the padded stash: float offset TWF + s*TWS + 20o + 4q.
  {
    const float* tb = &sdata[TWF + 20 * o];
    #pragma unroll
    for (int s = 0; s < 3; s++){
      #pragma unroll
      for (int qq = 0; qq < 4; qq++){
        float4 t = *(const float4*)&tb[s * TWS + 4 * qq];
        tw[(s*4+qq)*4+0] = t.x; tw[(s*4+qq)*4+1] = t.y;
        tw[(s*4+qq)*4+2] = t.z; tw[(s*4+qq)*4+3] = t.w;
      }
    }
  }
  #pragma unroll
  for (int g = 0; g < 2; g++){
    const int quad = 2 * sub + g;    // quad q holds rows blk*16 + 4q + {0..3}
    const float* base = x + (rowbase + 4 * g) * 1024 + 8 * o;
    float4 a0 = *(const float4*)(base        );
    float4 b0 = *(const float4*)(base +    4 );
    float4 a1 = *(const float4*)(base + 1024 );
    float4 b1 = *(const float4*)(base + 1028 );
    float4 a2 = *(const float4*)(base + 2048 );
    float4 b2 = *(const float4*)(base + 2052 );
    float4 a3 = *(const float4*)(base + 3072 );
    float4 b3 = *(const float4*)(base + 3076 );
    u64 v01[8], v23[8];
    v01[0]=pk2(a0.x,a1.x); v01[1]=pk2(a0.y,a1.y); v01[2]=pk2(a0.z,a1.z); v01[3]=pk2(a0.w,a1.w);
    v01[4]=pk2(b0.x,b1.x); v01[5]=pk2(b0.y,b1.y); v01[6]=pk2(b0.z,b1.z); v01[7]=pk2(b0.w,b1.w);
    v23[0]=pk2(a2.x,a3.x); v23[1]=pk2(a2.y,a3.y); v23[2]=pk2(a2.z,a3.z); v23[3]=pk2(a2.w,a3.w);
    v23[4]=pk2(b2.x,b3.x); v23[5]=pk2(b2.y,b3.y); v23[6]=pk2(b2.z,b3.z); v23[7]=pk2(b2.w,b3.w);

    radix8q(v01, v23, tw);

    #pragma unroll
    for (int c = 0; c < 8; c++){
      ulonglong2 u; u.x = v01[c]; u.y = v23[c];
      *(ulonglong2*)&sdata[widx(8 * o + c, quad)] = u;
    }
  }

  // Hoist P2 twiddle loads above the barrier (independent of the data tile).
  const int bb = o >> 3, j = o & 7;
  load_tw(tw4, 3, 32 * bb + j, 8, tw);
  __syncthreads();

  // ================= PASS 2: stages 3-5 (stride 8,16,32) ====================
  {
    #pragma unroll
    for (int g = 0; g < 2; g++){
      const int quad = 2 * sub + g;
      u64 v01[8], v23[8];
      #pragma unroll
      for (int k = 0; k < 8; k++){
        ulonglong2 u = *(ulonglong2*)&sdata[widx(64 * bb + 8 * k + j, quad)];
        v01[k] = u.x; v23[k] = u.y;
      }
      radix8q(v01, v23, tw);
      #pragma unroll
      for (int k = 0; k < 8; k++){
        ulonglong2 u; u.x = v01[k]; u.y = v23[k];
        *(ulonglong2*)&sdata[widx(64 * bb + 8 * k + j, quad)] = u;
      }
    }
  }

  // Hoist bias loads above the barrier (independent of the data tile).
  const int j2 = tid & 63;
  const int q  = tid >> 6;
  float bs[16];
  #pragma unroll
  for (int m = 0; m < 16; m++) bs[m] = bias[j2 + 64 * m];
  __syncthreads();

  // ====== PASS 3: stages 6-9 (stride 64,128,256,512) + bias -> global =======
  // Thread owns pos = j2 + 64m, m=0..15, for one quad (4 rows). All four
  // stages run in registers; smem data tile is read exactly once. Twiddle
  // LDGs here are lane-coalesced (4 wf/inst) — keep them as LDG (R8 lesson).
  {
    u64 v01[16], v23[16];
    #pragma unroll
    for (int m = 0; m < 16; m++){
      ulonglong2 u = *(ulonglong2*)&sdata[widx(j2 + 64 * m, q)];
      v01[m] = u.x; v23[m] = u.y;
    }
    // stage 6 (S=64): pairs (2r, 2r+1); tw idx = 64r + j2
    #pragma unroll
    for (int r = 0; r < 8; r++){
      float4 t = tw4[6 * 512 + 64 * r + j2];
      float tm[4] = {t.x, t.y, t.z, t.w};
      bflyq(v01[2*r], v23[2*r], v01[2*r+1], v23[2*r+1], tm);
    }
    // stage 7 (S=128): pairs (4r+h, 4r+h+2); tw idx = 128r + 64h + j2
    #pragma unroll
    for (int r = 0; r < 4; r++){
      #pragma unroll
      for (int h = 0; h < 2; h++){
        float4 t = tw4[7 * 512 + 128 * r + 64 * h + j2];
        float tm[4] = {t.x, t.y, t.z, t.w};
        const int m0 = 4 * r + h;
        bflyq(v01[m0], v23[m0], v01[m0+2], v23[m0+2], tm);
      }
    }
    // stage 8 (S=256): pairs (8r+h, 8r+h+4); tw idx = 256r + 64h + j2
    #pragma unroll
    for (int r = 0; r < 2; r++){
      #pragma unroll
      for (int h = 0; h < 4; h++){
        float4 t = tw4[8 * 512 + 256 * r + 64 * h + j2];
        float tm[4] = {t.x, t.y, t.z, t.w};
        const int m0 = 8 * r + h;
        bflyq(v01[m0], v23[m0], v01[m0+4], v23[m0+4], tm);
      }
    }
    // stage 9 (S=512): pairs (h, h+8); tw idx = 64h + j2
    #pragma unroll
    for (int h = 0; h < 8; h++){
      float4 t = tw4[9 * 512 + 64 * h + j2];
      float tm[4] = {t.x, t.y, t.z, t.w};
      bflyq(v01[h], v23[h], v01[h+8], v23[h+8], tm);
    }
    // bias + store (lanes j2 consecutive -> 128B-coalesced STG.32)
    const long long r0 = (long long)blockIdx.x * 16 + 4 * q;
    float* obase = out + r0 * 1024 + j2;
    #pragma unroll
    for (int m = 0; m < 16; m++){
      u64 b2 = pk2(bs[m], bs[m]);
      u64 ylo = add2(v01[m], b2);
      u64 yhi = add2(v23[m], b2);
      float f0, f1, f2, f3;
      upk2(ylo, f0, f1); upk2(yhi, f2, f3);
      float* op = obase + 64 * m;
      op[0]    = f0;
      op[1024] = f1;
      op[2048] = f2;
      op[3072] = f3;
    }
  }
}

extern "C" void kernel_launch(void* const* d_in, const int* in_sizes, int n_in,
                              void* d_out, int out_size)
{
  const float* x    = (const float*)d_in[0];   // (32768, 1024) f32
  const float* tw   = (const float*)d_in[1];   // (1, 10, 512, 2, 2) f32
  const float* bias = (const float*)d_in[2];   // (1024,) f32
  float* out = (float*)d_out;                  // (32768, 1024) f32

  const int batch = in_sizes[0] / 1024;
  const int smem_bytes = (16384 + 3 * 2560) * 4;   // 64KB data + 30KB tw stash

  cudaFuncSetAttribute(butterfly_kernel,
                       cudaFuncAttributeMaxDynamicSharedMemorySize, smem_bytes);
  butterfly_kernel<<<batch / 16, 256, smem_bytes>>>(x, tw, bias, out);
}